// round 1
// baseline (speedup 1.0000x reference)
#include <cuda_runtime.h>
#include <math.h>

#define BATCH 2
#define SEQ   2048
#define NH    16
#define DHEAD 64
#define DM    1024
#define TTOK  (BATCH*SEQ)
#define BHN   (BATCH*NH)
#define ATTN_OFF ((size_t)BATCH*SEQ*DM)
#define LN_EPS 1e-5f

// Scratch (device globals are the sanctioned scratch mechanism)
__device__ float g_q[(size_t)BHN*SEQ*DHEAD];   // [B,H,S,64]
__device__ float g_k[(size_t)BHN*SEQ*DHEAD];
__device__ float g_v[(size_t)BHN*SEQ*DHEAD];
__device__ float g_ctx[(size_t)TTOK*DM];        // [T, H*64]
__device__ float g_x[(size_t)TTOK*DM];          // pre-LN

// ---------------------------------------------------------------------------
// Generic 64x64x16 tiled SGEMM (4x4 microtile / thread, 256 threads).
// mode 0/1/2 : out = X@W+b  written into g_q/g_k/g_v in [B,H,S,64] layout
// mode 3     : out = g_ctx@W + b + resid  written into g_x [T,DM]
// ---------------------------------------------------------------------------
__global__ void __launch_bounds__(256) proj_kernel(
    const float* __restrict__ X, const float* __restrict__ W,
    const float* __restrict__ bias, const float* __restrict__ resid,
    int mode)
{
    __shared__ float As[16][68];   // [k][m]
    __shared__ float Bs[16][68];   // [k][n]

    const float* in = (mode == 3) ? g_ctx : X;
    float* out = (mode == 0) ? g_q : (mode == 1) ? g_k : (mode == 2) ? g_v : g_x;

    const int tid = threadIdx.x;
    const int m0 = blockIdx.y * 64;
    const int n0 = blockIdx.x * 64;
    const int tx = tid & 15, ty = tid >> 4;
    const int arow = tid >> 2, ak4 = (tid & 3) << 2;
    const int brow = tid >> 4, bc4 = (tid & 15) << 2;

    float acc[4][4] = {};

    for (int k0 = 0; k0 < DM; k0 += 16) {
        float4 a = *(const float4*)(in + (size_t)(m0 + arow) * DM + k0 + ak4);
        As[ak4+0][arow] = a.x; As[ak4+1][arow] = a.y;
        As[ak4+2][arow] = a.z; As[ak4+3][arow] = a.w;
        *(float4*)&Bs[brow][bc4] =
            *(const float4*)(W + (size_t)(k0 + brow) * DM + n0 + bc4);
        __syncthreads();
        #pragma unroll
        for (int kk = 0; kk < 16; kk++) {
            float4 ra = *(const float4*)&As[kk][ty << 2];
            float4 rb = *(const float4*)&Bs[kk][tx << 2];
            float pa[4] = {ra.x, ra.y, ra.z, ra.w};
            float pb[4] = {rb.x, rb.y, rb.z, rb.w};
            #pragma unroll
            for (int i = 0; i < 4; i++)
                #pragma unroll
                for (int j = 0; j < 4; j++)
                    acc[i][j] += pa[i] * pb[j];
        }
        __syncthreads();
    }

    float4 bi = *(const float4*)(bias + n0 + (tx << 2));
    #pragma unroll
    for (int i = 0; i < 4; i++) {
        int m = m0 + (ty << 2) + i;
        float4 o;
        o.x = acc[i][0] + bi.x; o.y = acc[i][1] + bi.y;
        o.z = acc[i][2] + bi.z; o.w = acc[i][3] + bi.w;
        if (mode != 3) {
            // [B,H,S,64] layout; n0 is a multiple of 64 so the whole block is one head
            int h = n0 >> 6;
            int b = m >> 11, s = m & (SEQ - 1);
            *(float4*)(out + ((size_t)(b * NH + h) * SEQ + s) * DHEAD + (tx << 2)) = o;
        } else {
            float4 r = *(const float4*)(resid + (size_t)m * DM + n0 + (tx << 2));
            o.x += r.x; o.y += r.y; o.z += r.z; o.w += r.w;
            *(float4*)(out + (size_t)m * DM + n0 + (tx << 2)) = o;
        }
    }
}

// ---------------------------------------------------------------------------
// scores = (q @ k^T) * 1/8, masked.  K=64 fits entirely in smem (single stage).
// Writes straight into the attn region of d_out.
// ---------------------------------------------------------------------------
__global__ void __launch_bounds__(256) scores_kernel(
    const unsigned char* __restrict__ mask, float* __restrict__ attn)
{
    __shared__ float Qs[64][68];   // [k][m]
    __shared__ float Ks[64][68];   // [k][n]
    const int tid = threadIdx.x;
    const int bh = blockIdx.z;
    const int i0 = blockIdx.y * 64;
    const int j0 = blockIdx.x * 64;

    const float* qb = g_q + ((size_t)bh * SEQ + i0) * DHEAD;
    const float* kb = g_k + ((size_t)bh * SEQ + j0) * DHEAD;

    #pragma unroll
    for (int r = 0; r < 4; r++) {
        int f = tid + r * 256;           // float4 index within 64x64 tile
        int row = f >> 4;
        int c4 = (f & 15) << 2;
        float4 a = *(const float4*)(qb + (size_t)row * DHEAD + c4);
        Qs[c4+0][row] = a.x; Qs[c4+1][row] = a.y;
        Qs[c4+2][row] = a.z; Qs[c4+3][row] = a.w;
        float4 b = *(const float4*)(kb + (size_t)row * DHEAD + c4);
        Ks[c4+0][row] = b.x; Ks[c4+1][row] = b.y;
        Ks[c4+2][row] = b.z; Ks[c4+3][row] = b.w;
    }
    __syncthreads();

    const int tx = tid & 15, ty = tid >> 4;
    float acc[4][4] = {};
    #pragma unroll 16
    for (int kk = 0; kk < 64; kk++) {
        float4 ra = *(const float4*)&Qs[kk][ty << 2];
        float4 rb = *(const float4*)&Ks[kk][tx << 2];
        float pa[4] = {ra.x, ra.y, ra.z, ra.w};
        float pb[4] = {rb.x, rb.y, rb.z, rb.w};
        #pragma unroll
        for (int i = 0; i < 4; i++)
            #pragma unroll
            for (int j = 0; j < 4; j++)
                acc[i][j] += pa[i] * pb[j];
    }

    const int b = bh >> 4;
    const float scale = 0.125f;   // 1/sqrt(64)
    #pragma unroll
    for (int i = 0; i < 4; i++) {
        int ig = i0 + (ty << 2) + i;
        uchar4 mk = *(const uchar4*)(mask + ((size_t)b * SEQ + ig) * SEQ + j0 + (tx << 2));
        float4 o;
        o.x = mk.x ? -1e9f : acc[i][0] * scale;
        o.y = mk.y ? -1e9f : acc[i][1] * scale;
        o.z = mk.z ? -1e9f : acc[i][2] * scale;
        o.w = mk.w ? -1e9f : acc[i][3] * scale;
        *(float4*)(attn + ((size_t)bh * SEQ + ig) * SEQ + j0 + (tx << 2)) = o;
    }
}

// ---------------------------------------------------------------------------
// Row softmax in-place over the attn region. One block (128 thr) per row.
// ---------------------------------------------------------------------------
__global__ void __launch_bounds__(128) softmax_kernel(float* __restrict__ attn)
{
    const size_t row = blockIdx.x;
    float* p = attn + row * SEQ;
    const int tid = threadIdx.x;

    float4 v[4];
    float mx = -3.0e38f;
    #pragma unroll
    for (int r = 0; r < 4; r++) {
        v[r] = *(const float4*)(p + ((size_t)(r * 128 + tid)) * 4);
        mx = fmaxf(mx, fmaxf(fmaxf(v[r].x, v[r].y), fmaxf(v[r].z, v[r].w)));
    }
    __shared__ float sm[4], ss[4];
    #pragma unroll
    for (int o = 16; o; o >>= 1) mx = fmaxf(mx, __shfl_xor_sync(0xffffffffu, mx, o));
    if ((tid & 31) == 0) sm[tid >> 5] = mx;
    __syncthreads();
    mx = fmaxf(fmaxf(sm[0], sm[1]), fmaxf(sm[2], sm[3]));

    float s = 0.f;
    #pragma unroll
    for (int r = 0; r < 4; r++) {
        v[r].x = __expf(v[r].x - mx);
        v[r].y = __expf(v[r].y - mx);
        v[r].z = __expf(v[r].z - mx);
        v[r].w = __expf(v[r].w - mx);
        s += v[r].x + v[r].y + v[r].z + v[r].w;
    }
    #pragma unroll
    for (int o = 16; o; o >>= 1) s += __shfl_xor_sync(0xffffffffu, s, o);
    if ((tid & 31) == 0) ss[tid >> 5] = s;
    __syncthreads();
    s = ss[0] + ss[1] + ss[2] + ss[3];
    float inv = 1.0f / s;
    #pragma unroll
    for (int r = 0; r < 4; r++) {
        v[r].x *= inv; v[r].y *= inv; v[r].z *= inv; v[r].w *= inv;
        *(float4*)(p + ((size_t)(r * 128 + tid)) * 4) = v[r];
    }
}

// ---------------------------------------------------------------------------
// context = attn @ v   (M=2048, N=64, K=2048 per (b,h)); writes g_ctx [T, H*64]
// ---------------------------------------------------------------------------
__global__ void __launch_bounds__(256) ctx_kernel(const float* __restrict__ attn)
{
    __shared__ float As[16][68];   // [k][m]
    __shared__ float Bs[16][68];   // [k][n]
    const int tid = threadIdx.x;
    const int bh = blockIdx.y;
    const int m0 = blockIdx.x * 64;

    const float* ab = attn + ((size_t)bh * SEQ + m0) * SEQ;
    const float* vb = g_v + (size_t)bh * SEQ * DHEAD;

    const int arow = tid >> 2, ak4 = (tid & 3) << 2;
    const int brow = tid >> 4, bc4 = (tid & 15) << 2;
    const int tx = tid & 15, ty = tid >> 4;

    float acc[4][4] = {};
    for (int k0 = 0; k0 < SEQ; k0 += 16) {
        float4 a = *(const float4*)(ab + (size_t)arow * SEQ + k0 + ak4);
        As[ak4+0][arow] = a.x; As[ak4+1][arow] = a.y;
        As[ak4+2][arow] = a.z; As[ak4+3][arow] = a.w;
        *(float4*)&Bs[brow][bc4] =
            *(const float4*)(vb + (size_t)(k0 + brow) * DHEAD + bc4);
        __syncthreads();
        #pragma unroll
        for (int kk = 0; kk < 16; kk++) {
            float4 ra = *(const float4*)&As[kk][ty << 2];
            float4 rb = *(const float4*)&Bs[kk][tx << 2];
            float pa[4] = {ra.x, ra.y, ra.z, ra.w};
            float pb[4] = {rb.x, rb.y, rb.z, rb.w};
            #pragma unroll
            for (int i = 0; i < 4; i++)
                #pragma unroll
                for (int j = 0; j < 4; j++)
                    acc[i][j] += pa[i] * pb[j];
        }
        __syncthreads();
    }

    const int b = bh >> 4, h = bh & 15;
    #pragma unroll
    for (int i = 0; i < 4; i++) {
        int t = b * SEQ + m0 + (ty << 2) + i;
        float4 o = make_float4(acc[i][0], acc[i][1], acc[i][2], acc[i][3]);
        *(float4*)(g_ctx + (size_t)t * DM + h * DHEAD + (tx << 2)) = o;
    }
}

// ---------------------------------------------------------------------------
// LayerNorm over g_x rows -> out region of d_out. One block (256 thr) / token.
// ---------------------------------------------------------------------------
__global__ void __launch_bounds__(256) ln_kernel(
    const float* __restrict__ gamma, const float* __restrict__ beta,
    float* __restrict__ out)
{
    const int t = blockIdx.x;
    const int tid = threadIdx.x;
    float4 v = *(const float4*)(g_x + (size_t)t * DM + (tid << 2));
    float s  = v.x + v.y + v.z + v.w;
    float ss = v.x*v.x + v.y*v.y + v.z*v.z + v.w*v.w;

    __shared__ float r1[8], r2[8];
    #pragma unroll
    for (int o = 16; o; o >>= 1) {
        s  += __shfl_xor_sync(0xffffffffu, s, o);
        ss += __shfl_xor_sync(0xffffffffu, ss, o);
    }
    if ((tid & 31) == 0) { r1[tid >> 5] = s; r2[tid >> 5] = ss; }
    __syncthreads();
    float ts = 0.f, tss = 0.f;
    #pragma unroll
    for (int w = 0; w < 8; w++) { ts += r1[w]; tss += r2[w]; }

    float mu  = ts * (1.0f / DM);
    float var = tss * (1.0f / DM) - mu * mu;
    float inv = rsqrtf(var + LN_EPS);

    float4 g  = *(const float4*)(gamma + (tid << 2));
    float4 be = *(const float4*)(beta  + (tid << 2));
    float4 o;
    o.x = (v.x - mu) * inv * g.x + be.x;
    o.y = (v.y - mu) * inv * g.y + be.y;
    o.z = (v.z - mu) * inv * g.z + be.z;
    o.w = (v.w - mu) * inv * g.w + be.w;
    *(float4*)(out + (size_t)t * DM + (tid << 2)) = o;
}

// ---------------------------------------------------------------------------
extern "C" void kernel_launch(void* const* d_in, const int* in_sizes, int n_in,
                              void* d_out, int out_size)
{
    const float* Q  = (const float*)d_in[0];
    const float* K  = (const float*)d_in[1];
    const float* V  = (const float*)d_in[2];
    const unsigned char* mask = (const unsigned char*)d_in[3];
    const float* Wq = (const float*)d_in[4];
    const float* bq = (const float*)d_in[5];
    const float* Wk = (const float*)d_in[6];
    const float* bk = (const float*)d_in[7];
    const float* Wv = (const float*)d_in[8];
    const float* bv = (const float*)d_in[9];
    const float* Wo = (const float*)d_in[10];
    const float* bo = (const float*)d_in[11];
    const float* gamma = (const float*)d_in[12];
    const float* beta  = (const float*)d_in[13];

    float* out  = (float*)d_out;
    float* attn = out + ATTN_OFF;

    dim3 gProj(DM / 64, TTOK / 64);
    proj_kernel<<<gProj, 256>>>(Q, Wq, bq, nullptr, 0);
    proj_kernel<<<gProj, 256>>>(K, Wk, bk, nullptr, 1);
    proj_kernel<<<gProj, 256>>>(V, Wv, bv, nullptr, 2);
    scores_kernel<<<dim3(SEQ / 64, SEQ / 64, BHN), 256>>>(mask, attn);
    softmax_kernel<<<BHN * SEQ, 128>>>(attn);
    ctx_kernel<<<dim3(SEQ / 64, BHN), 256>>>(attn);
    proj_kernel<<<gProj, 256>>>(Q /*residual*/, Wo, bo, Q, 3);
    ln_kernel<<<TTOK, 256>>>(gamma, beta, out);
}

// round 2
// speedup vs baseline: 1.8768x; 1.8768x over previous
#include <cuda_runtime.h>
#include <math.h>

#define BATCH 2
#define SEQ   2048
#define NH    16
#define DHEAD 64
#define DM    1024
#define TTOK  (BATCH*SEQ)
#define BHN   (BATCH*NH)
#define ATTN_OFF ((size_t)BATCH*SEQ*DM)
#define LN_EPS 1e-5f

__device__ float g_q[(size_t)BHN*SEQ*DHEAD];   // [B,H,S,64]
__device__ float g_k[(size_t)BHN*SEQ*DHEAD];
__device__ float g_v[(size_t)BHN*SEQ*DHEAD];
__device__ float g_ctx[(size_t)TTOK*DM];        // [T, H*64]
__device__ float g_x[(size_t)TTOK*DM];          // pre-LN

// ===========================================================================
// Fused QKV projection: out = X @ W + b, scattered to [B,H,S,64].
// 128x128 tile, K-chunk 16, 8x8 microtile, 256 threads, reg-prefetch pipeline.
// blockIdx.z in {0,1,2} selects Q/K/V.
// ===========================================================================
__global__ void __launch_bounds__(256) qkv_kernel(
    const float* __restrict__ Qin, const float* __restrict__ Kin,
    const float* __restrict__ Vin,
    const float* __restrict__ Wq, const float* __restrict__ Wk,
    const float* __restrict__ Wv,
    const float* __restrict__ bq, const float* __restrict__ bk,
    const float* __restrict__ bv)
{
    __shared__ float As[16][132];
    __shared__ float Bs[16][132];

    const int z = blockIdx.z;
    const float* X    = (z == 0) ? Qin : (z == 1) ? Kin : Vin;
    const float* W    = (z == 0) ? Wq  : (z == 1) ? Wk  : Wv;
    const float* bias = (z == 0) ? bq  : (z == 1) ? bk  : bv;
    float* out        = (z == 0) ? g_q : (z == 1) ? g_k : g_v;

    const int tid = threadIdx.x;
    const int m0 = blockIdx.y * 128;
    const int n0 = blockIdx.x * 128;
    const int tx = tid & 15, ty = tid >> 4;

    const int ar = tid >> 2, ak = (tid & 3) << 2;   // A: row, k-col4
    const int br = tid >> 5, bn = (tid & 31) << 2;  // B: k-row, n-col4

    const float* Ap = X + (size_t)(m0 + ar) * DM + ak;
    const float* Bp = W + (size_t)br * DM + n0 + bn;

    float acc[8][8] = {};
    float4 pa0, pa1, pb0, pb1;

    pa0 = *(const float4*)(Ap);
    pa1 = *(const float4*)(Ap + (size_t)64 * DM);
    pb0 = *(const float4*)(Bp);
    pb1 = *(const float4*)(Bp + (size_t)8 * DM);

    #define QKV_STS() do { \
        As[ak+0][ar] = pa0.x; As[ak+1][ar] = pa0.y; \
        As[ak+2][ar] = pa0.z; As[ak+3][ar] = pa0.w; \
        As[ak+0][ar+64] = pa1.x; As[ak+1][ar+64] = pa1.y; \
        As[ak+2][ar+64] = pa1.z; As[ak+3][ar+64] = pa1.w; \
        *(float4*)&Bs[br][bn]   = pb0; \
        *(float4*)&Bs[br+8][bn] = pb1; } while(0)

    #define QKV_COMPUTE() do { \
        _Pragma("unroll") \
        for (int kk = 0; kk < 16; kk++) { \
            float a[8], b[8]; \
            *(float4*)&a[0] = *(const float4*)&As[kk][ty*8]; \
            *(float4*)&a[4] = *(const float4*)&As[kk][ty*8+4]; \
            *(float4*)&b[0] = *(const float4*)&Bs[kk][tx*8]; \
            *(float4*)&b[4] = *(const float4*)&Bs[kk][tx*8+4]; \
            _Pragma("unroll") \
            for (int i = 0; i < 8; i++) \
                _Pragma("unroll") \
                for (int j = 0; j < 8; j++) \
                    acc[i][j] += a[i] * b[j]; \
        } } while(0)

    QKV_STS();
    __syncthreads();
    for (int k0 = 16; k0 < DM; k0 += 16) {
        pa0 = *(const float4*)(Ap + k0);
        pa1 = *(const float4*)(Ap + (size_t)64 * DM + k0);
        pb0 = *(const float4*)(Bp + (size_t)k0 * DM);
        pb1 = *(const float4*)(Bp + (size_t)(k0 + 8) * DM);
        QKV_COMPUTE();
        __syncthreads();
        QKV_STS();
        __syncthreads();
    }
    QKV_COMPUTE();

    // epilogue: scatter to [B,H,S,64]
    const int ncol = n0 + tx * 8;          // 8 cols, all within one head
    const int h = ncol >> 6;
    const int d = ncol & 63;
    float4 bi0 = *(const float4*)(bias + ncol);
    float4 bi1 = *(const float4*)(bias + ncol + 4);
    #pragma unroll
    for (int i = 0; i < 8; i++) {
        int m = m0 + ty * 8 + i;
        int b = m >> 11, s = m & (SEQ - 1);
        float* op = out + ((size_t)(b * NH + h) * SEQ + s) * DHEAD + d;
        float4 o0 = make_float4(acc[i][0]+bi0.x, acc[i][1]+bi0.y,
                                acc[i][2]+bi0.z, acc[i][3]+bi0.w);
        float4 o1 = make_float4(acc[i][4]+bi1.x, acc[i][5]+bi1.y,
                                acc[i][6]+bi1.z, acc[i][7]+bi1.w);
        *(float4*)op = o0;
        *(float4*)(op + 4) = o1;
    }
}

// ===========================================================================
// Output projection: g_x = g_ctx @ Wo + bo + residual. Same 128x128 SGEMM.
// ===========================================================================
__global__ void __launch_bounds__(256) oproj_kernel(
    const float* __restrict__ W, const float* __restrict__ bias,
    const float* __restrict__ resid)
{
    __shared__ float As[16][132];
    __shared__ float Bs[16][132];

    const int tid = threadIdx.x;
    const int m0 = blockIdx.y * 128;
    const int n0 = blockIdx.x * 128;
    const int tx = tid & 15, ty = tid >> 4;
    const int ar = tid >> 2, ak = (tid & 3) << 2;
    const int br = tid >> 5, bn = (tid & 31) << 2;

    const float* Ap = g_ctx + (size_t)(m0 + ar) * DM + ak;
    const float* Bp = W + (size_t)br * DM + n0 + bn;

    float acc[8][8] = {};
    float4 pa0, pa1, pb0, pb1;

    pa0 = *(const float4*)(Ap);
    pa1 = *(const float4*)(Ap + (size_t)64 * DM);
    pb0 = *(const float4*)(Bp);
    pb1 = *(const float4*)(Bp + (size_t)8 * DM);

    QKV_STS();
    __syncthreads();
    for (int k0 = 16; k0 < DM; k0 += 16) {
        pa0 = *(const float4*)(Ap + k0);
        pa1 = *(const float4*)(Ap + (size_t)64 * DM + k0);
        pb0 = *(const float4*)(Bp + (size_t)k0 * DM);
        pb1 = *(const float4*)(Bp + (size_t)(k0 + 8) * DM);
        QKV_COMPUTE();
        __syncthreads();
        QKV_STS();
        __syncthreads();
    }
    QKV_COMPUTE();

    const int ncol = n0 + tx * 8;
    float4 bi0 = *(const float4*)(bias + ncol);
    float4 bi1 = *(const float4*)(bias + ncol + 4);
    #pragma unroll
    for (int i = 0; i < 8; i++) {
        int m = m0 + ty * 8 + i;
        const float* rp = resid + (size_t)m * DM + ncol;
        float4 r0 = *(const float4*)rp;
        float4 r1 = *(const float4*)(rp + 4);
        float* op = g_x + (size_t)m * DM + ncol;
        *(float4*)op = make_float4(acc[i][0]+bi0.x+r0.x, acc[i][1]+bi0.y+r0.y,
                                   acc[i][2]+bi0.z+r0.z, acc[i][3]+bi0.w+r0.w);
        *(float4*)(op+4) = make_float4(acc[i][4]+bi1.x+r1.x, acc[i][5]+bi1.y+r1.y,
                                       acc[i][6]+bi1.z+r1.z, acc[i][7]+bi1.w+r1.w);
    }
}

// ===========================================================================
// scores = (q @ k^T) * 1/8 masked -> attn region. 128x128 tile, K=64 in 4
// chunks of 16, 8x8 microtile.
// ===========================================================================
__global__ void __launch_bounds__(256) scores_kernel(
    const unsigned char* __restrict__ mask, float* __restrict__ attn)
{
    __shared__ float As[16][132];
    __shared__ float Bs[16][132];

    const int tid = threadIdx.x;
    const int bh = blockIdx.z;
    const int i0 = blockIdx.y * 128;
    const int j0 = blockIdx.x * 128;
    const int tx = tid & 15, ty = tid >> 4;

    const int ar = tid >> 2, ak = (tid & 3) << 2;   // seq-row, d-col4 (both tiles)

    const float* Ap = g_q + ((size_t)bh * SEQ + i0 + ar) * DHEAD + ak;
    const float* Bp = g_k + ((size_t)bh * SEQ + j0 + ar) * DHEAD + ak;

    float acc[8][8] = {};
    float4 pa0, pa1, pb0, pb1;

    #define SC_LDG(k0) do { \
        pa0 = *(const float4*)(Ap + (k0)); \
        pa1 = *(const float4*)(Ap + (size_t)64 * DHEAD + (k0)); \
        pb0 = *(const float4*)(Bp + (k0)); \
        pb1 = *(const float4*)(Bp + (size_t)64 * DHEAD + (k0)); } while(0)

    #define SC_STS() do { \
        As[ak+0][ar] = pa0.x; As[ak+1][ar] = pa0.y; \
        As[ak+2][ar] = pa0.z; As[ak+3][ar] = pa0.w; \
        As[ak+0][ar+64] = pa1.x; As[ak+1][ar+64] = pa1.y; \
        As[ak+2][ar+64] = pa1.z; As[ak+3][ar+64] = pa1.w; \
        Bs[ak+0][ar] = pb0.x; Bs[ak+1][ar] = pb0.y; \
        Bs[ak+2][ar] = pb0.z; Bs[ak+3][ar] = pb0.w; \
        Bs[ak+0][ar+64] = pb1.x; Bs[ak+1][ar+64] = pb1.y; \
        Bs[ak+2][ar+64] = pb1.z; Bs[ak+3][ar+64] = pb1.w; } while(0)

    SC_LDG(0);
    SC_STS();
    __syncthreads();
    #pragma unroll
    for (int k0 = 16; k0 < DHEAD; k0 += 16) {
        SC_LDG(k0);
        QKV_COMPUTE();
        __syncthreads();
        SC_STS();
        __syncthreads();
    }
    QKV_COMPUTE();

    const int b = bh >> 4;
    const float scale = 0.125f;
    #pragma unroll
    for (int i = 0; i < 8; i++) {
        int ig = i0 + ty * 8 + i;
        const unsigned char* mp = mask + ((size_t)b * SEQ + ig) * SEQ + j0 + tx * 8;
        uchar4 m0v = *(const uchar4*)mp;
        uchar4 m1v = *(const uchar4*)(mp + 4);
        float* op = attn + ((size_t)bh * SEQ + ig) * SEQ + j0 + tx * 8;
        float4 o0, o1;
        o0.x = m0v.x ? -1e9f : acc[i][0]*scale;
        o0.y = m0v.y ? -1e9f : acc[i][1]*scale;
        o0.z = m0v.z ? -1e9f : acc[i][2]*scale;
        o0.w = m0v.w ? -1e9f : acc[i][3]*scale;
        o1.x = m1v.x ? -1e9f : acc[i][4]*scale;
        o1.y = m1v.y ? -1e9f : acc[i][5]*scale;
        o1.z = m1v.z ? -1e9f : acc[i][6]*scale;
        o1.w = m1v.w ? -1e9f : acc[i][7]*scale;
        *(float4*)op = o0;
        *(float4*)(op + 4) = o1;
    }
}

// ===========================================================================
// Row softmax in-place. One block (128 thr) per row.
// ===========================================================================
__global__ void __launch_bounds__(128) softmax_kernel(float* __restrict__ attn)
{
    const size_t row = blockIdx.x;
    float* p = attn + row * SEQ;
    const int tid = threadIdx.x;

    float4 v[4];
    float mx = -3.0e38f;
    #pragma unroll
    for (int r = 0; r < 4; r++) {
        v[r] = *(const float4*)(p + ((size_t)(r * 128 + tid)) * 4);
        mx = fmaxf(mx, fmaxf(fmaxf(v[r].x, v[r].y), fmaxf(v[r].z, v[r].w)));
    }
    __shared__ float sm[4], ss[4];
    #pragma unroll
    for (int o = 16; o; o >>= 1) mx = fmaxf(mx, __shfl_xor_sync(0xffffffffu, mx, o));
    if ((tid & 31) == 0) sm[tid >> 5] = mx;
    __syncthreads();
    mx = fmaxf(fmaxf(sm[0], sm[1]), fmaxf(sm[2], sm[3]));

    float s = 0.f;
    #pragma unroll
    for (int r = 0; r < 4; r++) {
        v[r].x = __expf(v[r].x - mx);
        v[r].y = __expf(v[r].y - mx);
        v[r].z = __expf(v[r].z - mx);
        v[r].w = __expf(v[r].w - mx);
        s += v[r].x + v[r].y + v[r].z + v[r].w;
    }
    #pragma unroll
    for (int o = 16; o; o >>= 1) s += __shfl_xor_sync(0xffffffffu, s, o);
    if ((tid & 31) == 0) ss[tid >> 5] = s;
    __syncthreads();
    s = ss[0] + ss[1] + ss[2] + ss[3];
    float inv = 1.0f / s;
    #pragma unroll
    for (int r = 0; r < 4; r++) {
        v[r].x *= inv; v[r].y *= inv; v[r].z *= inv; v[r].w *= inv;
        *(float4*)(p + ((size_t)(r * 128 + tid)) * 4) = v[r];
    }
}

// ===========================================================================
// context = attn @ v : per (b,h) M=2048,N=64,K=2048. 128x64 tile, K-chunk 32,
// 8x4 microtile, 256 threads.
// ===========================================================================
__global__ void __launch_bounds__(256) ctx_kernel(const float* __restrict__ attn)
{
    __shared__ float As[32][132];
    __shared__ float Bs[32][68];

    const int tid = threadIdx.x;
    const int bh = blockIdx.y;
    const int m0 = blockIdx.x * 128;
    const int nx = tid & 15, my = tid >> 4;

    const float* ab = attn + ((size_t)bh * SEQ + m0) * SEQ;
    const float* vb = g_v + (size_t)bh * SEQ * DHEAD;

    // A: 128 rows x 32 k = 1024 float4; 4 per thread. idx = tid + i*256
    // row = idx>>3 (0..127), kcol4 = (idx&7)*4
    const int a_r = tid >> 3, a_k = (tid & 7) << 2;
    // B: 32 rows x 64 = 512 float4; 2 per thread: row = tid>>4, +16; col4=(tid&15)*4
    const int b_r = tid >> 4, b_c = (tid & 15) << 2;

    float acc[8][4] = {};
    float4 pa[4], pb[2];

    #define CTX_LDG(k0) do { \
        _Pragma("unroll") \
        for (int i = 0; i < 4; i++) \
            pa[i] = *(const float4*)(ab + (size_t)(a_r + i*32) * SEQ + (k0) + a_k); \
        pb[0] = *(const float4*)(vb + (size_t)((k0) + b_r) * DHEAD + b_c); \
        pb[1] = *(const float4*)(vb + (size_t)((k0) + b_r + 16) * DHEAD + b_c); } while(0)

    #define CTX_STS() do { \
        _Pragma("unroll") \
        for (int i = 0; i < 4; i++) { \
            As[a_k+0][a_r + i*32] = pa[i].x; As[a_k+1][a_r + i*32] = pa[i].y; \
            As[a_k+2][a_r + i*32] = pa[i].z; As[a_k+3][a_r + i*32] = pa[i].w; } \
        *(float4*)&Bs[b_r][b_c]    = pb[0]; \
        *(float4*)&Bs[b_r+16][b_c] = pb[1]; } while(0)

    #define CTX_COMPUTE() do { \
        _Pragma("unroll") \
        for (int kk = 0; kk < 32; kk++) { \
            float a[8], b[4]; \
            *(float4*)&a[0] = *(const float4*)&As[kk][my*8]; \
            *(float4*)&a[4] = *(const float4*)&As[kk][my*8+4]; \
            *(float4*)&b[0] = *(const float4*)&Bs[kk][nx*4]; \
            _Pragma("unroll") \
            for (int i = 0; i < 8; i++) \
                _Pragma("unroll") \
                for (int j = 0; j < 4; j++) \
                    acc[i][j] += a[i] * b[j]; \
        } } while(0)

    CTX_LDG(0);
    CTX_STS();
    __syncthreads();
    for (int k0 = 32; k0 < SEQ; k0 += 32) {
        CTX_LDG(k0);
        CTX_COMPUTE();
        __syncthreads();
        CTX_STS();
        __syncthreads();
    }
    CTX_COMPUTE();

    const int b = bh >> 4, h = bh & 15;
    #pragma unroll
    for (int i = 0; i < 8; i++) {
        int t = b * SEQ + m0 + my * 8 + i;
        *(float4*)(g_ctx + (size_t)t * DM + h * DHEAD + nx * 4) =
            make_float4(acc[i][0], acc[i][1], acc[i][2], acc[i][3]);
    }
}

// ===========================================================================
// LayerNorm over g_x rows -> out region of d_out.
// ===========================================================================
__global__ void __launch_bounds__(256) ln_kernel(
    const float* __restrict__ gamma, const float* __restrict__ beta,
    float* __restrict__ out)
{
    const int t = blockIdx.x;
    const int tid = threadIdx.x;
    float4 v = *(const float4*)(g_x + (size_t)t * DM + (tid << 2));
    float s  = v.x + v.y + v.z + v.w;
    float ss = v.x*v.x + v.y*v.y + v.z*v.z + v.w*v.w;

    __shared__ float r1[8], r2[8];
    #pragma unroll
    for (int o = 16; o; o >>= 1) {
        s  += __shfl_xor_sync(0xffffffffu, s, o);
        ss += __shfl_xor_sync(0xffffffffu, ss, o);
    }
    if ((tid & 31) == 0) { r1[tid >> 5] = s; r2[tid >> 5] = ss; }
    __syncthreads();
    float ts = 0.f, tss = 0.f;
    #pragma unroll
    for (int w = 0; w < 8; w++) { ts += r1[w]; tss += r2[w]; }

    float mu  = ts * (1.0f / DM);
    float var = tss * (1.0f / DM) - mu * mu;
    float inv = rsqrtf(var + LN_EPS);

    float4 g  = *(const float4*)(gamma + (tid << 2));
    float4 be = *(const float4*)(beta  + (tid << 2));
    float4 o;
    o.x = (v.x - mu) * inv * g.x + be.x;
    o.y = (v.y - mu) * inv * g.y + be.y;
    o.z = (v.z - mu) * inv * g.z + be.z;
    o.w = (v.w - mu) * inv * g.w + be.w;
    *(float4*)(out + (size_t)t * DM + (tid << 2)) = o;
}

// ===========================================================================
extern "C" void kernel_launch(void* const* d_in, const int* in_sizes, int n_in,
                              void* d_out, int out_size)
{
    const float* Q  = (const float*)d_in[0];
    const float* K  = (const float*)d_in[1];
    const float* V  = (const float*)d_in[2];
    const unsigned char* mask = (const unsigned char*)d_in[3];
    const float* Wq = (const float*)d_in[4];
    const float* bq = (const float*)d_in[5];
    const float* Wk = (const float*)d_in[6];
    const float* bk = (const float*)d_in[7];
    const float* Wv = (const float*)d_in[8];
    const float* bv = (const float*)d_in[9];
    const float* Wo = (const float*)d_in[10];
    const float* bo = (const float*)d_in[11];
    const float* gamma = (const float*)d_in[12];
    const float* beta  = (const float*)d_in[13];

    float* out  = (float*)d_out;
    float* attn = out + ATTN_OFF;

    qkv_kernel<<<dim3(DM/128, TTOK/128, 3), 256>>>(Q, K, V, Wq, Wk, Wv, bq, bk, bv);
    scores_kernel<<<dim3(SEQ/128, SEQ/128, BHN), 256>>>(mask, attn);
    softmax_kernel<<<BHN * SEQ, 128>>>(attn);
    ctx_kernel<<<dim3(SEQ/128, BHN), 256>>>(attn);
    oproj_kernel<<<dim3(DM/128, TTOK/128), 256>>>(Wo, bo, Q);
    ln_kernel<<<TTOK, 256>>>(gamma, beta, out);
}

// round 3
// speedup vs baseline: 3.2936x; 1.7549x over previous
#include <cuda_runtime.h>
#include <math.h>

#define BATCH 2
#define SEQ   2048
#define NH    16
#define DHEAD 64
#define DM    1024
#define TTOK  (BATCH*SEQ)
#define BHN   (BATCH*NH)
#define ATTN_OFF ((size_t)BATCH*SEQ*DM)
#define LN_EPS 1e-5f

__device__ float g_q[(size_t)BHN*SEQ*DHEAD];   // [B,H,S,64]
__device__ float g_k[(size_t)BHN*SEQ*DHEAD];
__device__ float g_v[(size_t)BHN*SEQ*DHEAD];
__device__ float g_ctx[(size_t)TTOK*DM];        // [T, H*64]
__device__ float g_x[(size_t)TTOK*DM];          // pre-LN

__device__ __forceinline__ unsigned tf32(float f) {
    unsigned u;
    asm("cvt.rna.tf32.f32 %0, %1;" : "=r"(u) : "f"(f));
    return u;
}

#define MMA(d, a, b) \
    asm volatile("mma.sync.aligned.m16n8k8.row.col.f32.tf32.tf32.f32 " \
        "{%0,%1,%2,%3}, {%4,%5,%6,%7}, {%8,%9}, {%0,%1,%2,%3};" \
        : "+f"((d)[0]), "+f"((d)[1]), "+f"((d)[2]), "+f"((d)[3]) \
        : "r"((a)[0]), "r"((a)[1]), "r"((a)[2]), "r"((a)[3]), \
          "r"((b)[0]), "r"((b)[1]))

// One K=16 chunk of mma work. Requires locals: As[m][?], Bs[k][?], wm, wn, g, t, acc.
#define MMA_STEP(NMT, NNT) \
    _Pragma("unroll") \
    for (int kk = 0; kk < 16; kk += 8) { \
        unsigned af[NMT][4]; unsigned bf[NNT][2]; \
        _Pragma("unroll") \
        for (int mt = 0; mt < NMT; mt++) { \
            int mr = wm + mt*16 + g; \
            af[mt][0] = As[mr][kk+t];   af[mt][1] = As[mr+8][kk+t]; \
            af[mt][2] = As[mr][kk+t+4]; af[mt][3] = As[mr+8][kk+t+4]; \
        } \
        _Pragma("unroll") \
        for (int nt = 0; nt < NNT; nt++) { \
            bf[nt][0] = Bs[kk+t][wn + nt*8 + g]; \
            bf[nt][1] = Bs[kk+t+4][wn + nt*8 + g]; \
        } \
        _Pragma("unroll") \
        for (int mt = 0; mt < NMT; mt++) \
            _Pragma("unroll") \
            for (int nt = 0; nt < NNT; nt++) \
                MMA(acc[mt][nt], af[mt], bf[nt]); \
    }

// ===========================================================================
// QKV projection (tf32 mma): out = X @ W + b scattered to [B,H,S,64].
// Block 128x128, 8 warps (2m x 4n), warp tile 64x32, K-chunk 16.
// ===========================================================================
__global__ void __launch_bounds__(256) qkv_kernel(
    const float* __restrict__ Qin, const float* __restrict__ Kin,
    const float* __restrict__ Vin,
    const float* __restrict__ Wq, const float* __restrict__ Wk,
    const float* __restrict__ Wv,
    const float* __restrict__ bq, const float* __restrict__ bk,
    const float* __restrict__ bv)
{
    __shared__ unsigned As[128][20];
    __shared__ unsigned Bs[16][136];

    const int z = blockIdx.z;
    const float* X    = (z == 0) ? Qin : (z == 1) ? Kin : Vin;
    const float* W    = (z == 0) ? Wq  : (z == 1) ? Wk  : Wv;
    const float* bias = (z == 0) ? bq  : (z == 1) ? bk  : bv;
    float* out        = (z == 0) ? g_q : (z == 1) ? g_k : g_v;

    const int tid = threadIdx.x;
    const int lane = tid & 31, wid = tid >> 5;
    const int g = lane >> 2, t = lane & 3;
    const int wm = (wid & 1) << 6;
    const int wn = (wid >> 1) << 5;
    const int m0 = blockIdx.y * 128, n0 = blockIdx.x * 128;

    const int ar = tid >> 2, ak = (tid & 3) << 2;
    const int br = tid >> 5, bn = (tid & 31) << 2;

    const float* Ap = X + (size_t)(m0 + ar) * DM + ak;
    const float* Bp = W + (size_t)br * DM + n0 + bn;

    float acc[4][4][4] = {};
    float4 pa0, pa1, pb0, pb1;

    #define QKV_LDG(k0) do { \
        pa0 = *(const float4*)(Ap + (k0)); \
        pa1 = *(const float4*)(Ap + (size_t)64 * DM + (k0)); \
        pb0 = *(const float4*)(Bp + (size_t)(k0) * DM); \
        pb1 = *(const float4*)(Bp + (size_t)((k0) + 8) * DM); } while(0)

    #define QKV_STS() do { \
        *(uint4*)&As[ar][ak]    = make_uint4(tf32(pa0.x), tf32(pa0.y), tf32(pa0.z), tf32(pa0.w)); \
        *(uint4*)&As[ar+64][ak] = make_uint4(tf32(pa1.x), tf32(pa1.y), tf32(pa1.z), tf32(pa1.w)); \
        *(uint4*)&Bs[br][bn]    = make_uint4(tf32(pb0.x), tf32(pb0.y), tf32(pb0.z), tf32(pb0.w)); \
        *(uint4*)&Bs[br+8][bn]  = make_uint4(tf32(pb1.x), tf32(pb1.y), tf32(pb1.z), tf32(pb1.w)); } while(0)

    QKV_LDG(0);
    QKV_STS();
    __syncthreads();
    for (int k0 = 16; k0 < DM; k0 += 16) {
        QKV_LDG(k0);
        MMA_STEP(4, 4);
        __syncthreads();
        QKV_STS();
        __syncthreads();
    }
    MMA_STEP(4, 4);

    // epilogue: +bias, scatter to [B,H,S,64]
    #pragma unroll
    for (int nt = 0; nt < 4; nt++) {
        int c = n0 + wn + nt*8 + 2*t;
        int h = c >> 6, d = c & 63;
        float2 bi = *(const float2*)(bias + c);
        #pragma unroll
        for (int mt = 0; mt < 4; mt++) {
            int r = m0 + wm + mt*16 + g;
            int b = r >> 11, s = r & (SEQ - 1);
            float* op = out + ((size_t)(b * NH + h) * SEQ + s) * DHEAD + d;
            *(float2*)op = make_float2(acc[mt][nt][0] + bi.x, acc[mt][nt][1] + bi.y);
            op += (size_t)8 * DHEAD;
            *(float2*)op = make_float2(acc[mt][nt][2] + bi.x, acc[mt][nt][3] + bi.y);
        }
    }
}

// ===========================================================================
// Output projection (tf32 mma): g_x = g_ctx @ Wo + bo + residual.
// ===========================================================================
__global__ void __launch_bounds__(256) oproj_kernel(
    const float* __restrict__ W, const float* __restrict__ bias,
    const float* __restrict__ resid)
{
    __shared__ unsigned As[128][20];
    __shared__ unsigned Bs[16][136];

    const int tid = threadIdx.x;
    const int lane = tid & 31, wid = tid >> 5;
    const int g = lane >> 2, t = lane & 3;
    const int wm = (wid & 1) << 6;
    const int wn = (wid >> 1) << 5;
    const int m0 = blockIdx.y * 128, n0 = blockIdx.x * 128;

    const int ar = tid >> 2, ak = (tid & 3) << 2;
    const int br = tid >> 5, bn = (tid & 31) << 2;

    const float* Ap = g_ctx + (size_t)(m0 + ar) * DM + ak;
    const float* Bp = W + (size_t)br * DM + n0 + bn;

    float acc[4][4][4] = {};
    float4 pa0, pa1, pb0, pb1;

    QKV_LDG(0);
    QKV_STS();
    __syncthreads();
    for (int k0 = 16; k0 < DM; k0 += 16) {
        QKV_LDG(k0);
        MMA_STEP(4, 4);
        __syncthreads();
        QKV_STS();
        __syncthreads();
    }
    MMA_STEP(4, 4);

    #pragma unroll
    for (int nt = 0; nt < 4; nt++) {
        int c = n0 + wn + nt*8 + 2*t;
        float2 bi = *(const float2*)(bias + c);
        #pragma unroll
        for (int mt = 0; mt < 4; mt++) {
            int r = m0 + wm + mt*16 + g;
            float2 r0 = *(const float2*)(resid + (size_t)r * DM + c);
            float2 r1 = *(const float2*)(resid + (size_t)(r+8) * DM + c);
            *(float2*)(g_x + (size_t)r * DM + c) =
                make_float2(acc[mt][nt][0] + bi.x + r0.x, acc[mt][nt][1] + bi.y + r0.y);
            *(float2*)(g_x + (size_t)(r+8) * DM + c) =
                make_float2(acc[mt][nt][2] + bi.x + r1.x, acc[mt][nt][3] + bi.y + r1.y);
        }
    }
}

// ===========================================================================
// scores = (q @ k^T) / 8, masked (tf32 mma). Block 128x128, K=64 (4 chunks).
// ===========================================================================
__global__ void __launch_bounds__(256) scores_kernel(
    const unsigned char* __restrict__ mask, float* __restrict__ attn)
{
    __shared__ unsigned As[128][20];
    __shared__ unsigned Bs[16][138];

    const int tid = threadIdx.x;
    const int lane = tid & 31, wid = tid >> 5;
    const int g = lane >> 2, t = lane & 3;
    const int wm = (wid & 1) << 6;
    const int wn = (wid >> 1) << 5;
    const int bh = blockIdx.z;
    const int i0 = blockIdx.y * 128;
    const int j0 = blockIdx.x * 128;

    const int ar = tid >> 2, ak = (tid & 3) << 2;

    const float* Ap = g_q + ((size_t)bh * SEQ + i0 + ar) * DHEAD + ak;
    const float* Bp = g_k + ((size_t)bh * SEQ + j0 + ar) * DHEAD + ak;

    float acc[4][4][4] = {};
    float4 pa0, pa1, pb0, pb1;

    #define SC_LDG(k0) do { \
        pa0 = *(const float4*)(Ap + (k0)); \
        pa1 = *(const float4*)(Ap + (size_t)64 * DHEAD + (k0)); \
        pb0 = *(const float4*)(Bp + (k0)); \
        pb1 = *(const float4*)(Bp + (size_t)64 * DHEAD + (k0)); } while(0)

    #define SC_STS() do { \
        *(uint4*)&As[ar][ak]    = make_uint4(tf32(pa0.x), tf32(pa0.y), tf32(pa0.z), tf32(pa0.w)); \
        *(uint4*)&As[ar+64][ak] = make_uint4(tf32(pa1.x), tf32(pa1.y), tf32(pa1.z), tf32(pa1.w)); \
        Bs[ak+0][ar] = tf32(pb0.x); Bs[ak+1][ar] = tf32(pb0.y); \
        Bs[ak+2][ar] = tf32(pb0.z); Bs[ak+3][ar] = tf32(pb0.w); \
        Bs[ak+0][ar+64] = tf32(pb1.x); Bs[ak+1][ar+64] = tf32(pb1.y); \
        Bs[ak+2][ar+64] = tf32(pb1.z); Bs[ak+3][ar+64] = tf32(pb1.w); } while(0)

    SC_LDG(0);
    SC_STS();
    __syncthreads();
    #pragma unroll
    for (int k0 = 16; k0 < DHEAD; k0 += 16) {
        SC_LDG(k0);
        MMA_STEP(4, 4);
        __syncthreads();
        SC_STS();
        __syncthreads();
    }
    MMA_STEP(4, 4);

    const int b = bh >> 4;
    const float scale = 0.125f;
    #pragma unroll
    for (int nt = 0; nt < 4; nt++) {
        int c = j0 + wn + nt*8 + 2*t;
        #pragma unroll
        for (int mt = 0; mt < 4; mt++) {
            int r = i0 + wm + mt*16 + g;
            const unsigned char* mp0 = mask + ((size_t)b * SEQ + r) * SEQ + c;
            const unsigned char* mp1 = mask + ((size_t)b * SEQ + r + 8) * SEQ + c;
            float* op0 = attn + ((size_t)bh * SEQ + r) * SEQ + c;
            float* op1 = attn + ((size_t)bh * SEQ + r + 8) * SEQ + c;
            float2 o0, o1;
            o0.x = mp0[0] ? -1e9f : acc[mt][nt][0] * scale;
            o0.y = mp0[1] ? -1e9f : acc[mt][nt][1] * scale;
            o1.x = mp1[0] ? -1e9f : acc[mt][nt][2] * scale;
            o1.y = mp1[1] ? -1e9f : acc[mt][nt][3] * scale;
            *(float2*)op0 = o0;
            *(float2*)op1 = o1;
        }
    }
}

// ===========================================================================
// Row softmax in-place. One block (128 thr) per row.
// ===========================================================================
__global__ void __launch_bounds__(128) softmax_kernel(float* __restrict__ attn)
{
    const size_t row = blockIdx.x;
    float* p = attn + row * SEQ;
    const int tid = threadIdx.x;

    float4 v[4];
    float mx = -3.0e38f;
    #pragma unroll
    for (int r = 0; r < 4; r++) {
        v[r] = *(const float4*)(p + ((size_t)(r * 128 + tid)) * 4);
        mx = fmaxf(mx, fmaxf(fmaxf(v[r].x, v[r].y), fmaxf(v[r].z, v[r].w)));
    }
    __shared__ float sm[4], ss[4];
    #pragma unroll
    for (int o = 16; o; o >>= 1) mx = fmaxf(mx, __shfl_xor_sync(0xffffffffu, mx, o));
    if ((tid & 31) == 0) sm[tid >> 5] = mx;
    __syncthreads();
    mx = fmaxf(fmaxf(sm[0], sm[1]), fmaxf(sm[2], sm[3]));

    float s = 0.f;
    #pragma unroll
    for (int r = 0; r < 4; r++) {
        v[r].x = __expf(v[r].x - mx);
        v[r].y = __expf(v[r].y - mx);
        v[r].z = __expf(v[r].z - mx);
        v[r].w = __expf(v[r].w - mx);
        s += v[r].x + v[r].y + v[r].z + v[r].w;
    }
    #pragma unroll
    for (int o = 16; o; o >>= 1) s += __shfl_xor_sync(0xffffffffu, s, o);
    if ((tid & 31) == 0) ss[tid >> 5] = s;
    __syncthreads();
    s = ss[0] + ss[1] + ss[2] + ss[3];
    float inv = 1.0f / s;
    #pragma unroll
    for (int r = 0; r < 4; r++) {
        v[r].x *= inv; v[r].y *= inv; v[r].z *= inv; v[r].w *= inv;
        *(float4*)(p + ((size_t)(r * 128 + tid)) * 4) = v[r];
    }
}

// ===========================================================================
// context = attn @ v (tf32 mma): per (b,h) M=2048,N=64,K=2048.
// Block 128x64, 8 warps (4m x 2n), warp tile 32x32, K-chunk 16.
// ===========================================================================
__global__ void __launch_bounds__(256) ctx_kernel(const float* __restrict__ attn)
{
    __shared__ unsigned As[128][20];
    __shared__ unsigned Bs[16][72];

    const int tid = threadIdx.x;
    const int lane = tid & 31, wid = tid >> 5;
    const int g = lane >> 2, t = lane & 3;
    const int wm = (wid >> 1) << 5;    // 0,32,64,96
    const int wn = (wid & 1) << 5;     // 0,32
    const int bh = blockIdx.y;
    const int m0 = blockIdx.x * 128;

    const float* ab = attn + ((size_t)bh * SEQ + m0) * SEQ;
    const float* vb = g_v + (size_t)bh * SEQ * DHEAD;

    const int ar = tid >> 2, ak = (tid & 3) << 2;
    const int br = tid >> 4, bc = (tid & 15) << 2;

    float acc[2][4][4] = {};
    float4 pa0, pa1, pb;

    #define CTX_LDG(k0) do { \
        pa0 = *(const float4*)(ab + (size_t)ar * SEQ + (k0) + ak); \
        pa1 = *(const float4*)(ab + (size_t)(ar + 64) * SEQ + (k0) + ak); \
        pb  = *(const float4*)(vb + (size_t)((k0) + br) * DHEAD + bc); } while(0)

    #define CTX_STS() do { \
        *(uint4*)&As[ar][ak]    = make_uint4(tf32(pa0.x), tf32(pa0.y), tf32(pa0.z), tf32(pa0.w)); \
        *(uint4*)&As[ar+64][ak] = make_uint4(tf32(pa1.x), tf32(pa1.y), tf32(pa1.z), tf32(pa1.w)); \
        *(uint4*)&Bs[br][bc]    = make_uint4(tf32(pb.x), tf32(pb.y), tf32(pb.z), tf32(pb.w)); } while(0)

    CTX_LDG(0);
    CTX_STS();
    __syncthreads();
    for (int k0 = 16; k0 < SEQ; k0 += 16) {
        CTX_LDG(k0);
        MMA_STEP(2, 4);
        __syncthreads();
        CTX_STS();
        __syncthreads();
    }
    MMA_STEP(2, 4);

    const int b = bh >> 4, h = bh & 15;
    #pragma unroll
    for (int nt = 0; nt < 4; nt++) {
        int c = wn + nt*8 + 2*t;
        #pragma unroll
        for (int mt = 0; mt < 2; mt++) {
            int r = m0 + wm + mt*16 + g;
            size_t tok = (size_t)(b * SEQ + r);
            *(float2*)(g_ctx + tok * DM + h * DHEAD + c) =
                make_float2(acc[mt][nt][0], acc[mt][nt][1]);
            *(float2*)(g_ctx + (tok + 8) * DM + h * DHEAD + c) =
                make_float2(acc[mt][nt][2], acc[mt][nt][3]);
        }
    }
}

// ===========================================================================
// LayerNorm over g_x rows -> out region of d_out.
// ===========================================================================
__global__ void __launch_bounds__(256) ln_kernel(
    const float* __restrict__ gamma, const float* __restrict__ beta,
    float* __restrict__ out)
{
    const int tk = blockIdx.x;
    const int tid = threadIdx.x;
    float4 v = *(const float4*)(g_x + (size_t)tk * DM + (tid << 2));
    float s  = v.x + v.y + v.z + v.w;
    float ss = v.x*v.x + v.y*v.y + v.z*v.z + v.w*v.w;

    __shared__ float r1[8], r2[8];
    #pragma unroll
    for (int o = 16; o; o >>= 1) {
        s  += __shfl_xor_sync(0xffffffffu, s, o);
        ss += __shfl_xor_sync(0xffffffffu, ss, o);
    }
    if ((tid & 31) == 0) { r1[tid >> 5] = s; r2[tid >> 5] = ss; }
    __syncthreads();
    float ts = 0.f, tss = 0.f;
    #pragma unroll
    for (int w = 0; w < 8; w++) { ts += r1[w]; tss += r2[w]; }

    float mu  = ts * (1.0f / DM);
    float var = tss * (1.0f / DM) - mu * mu;
    float inv = rsqrtf(var + LN_EPS);

    float4 ga = *(const float4*)(gamma + (tid << 2));
    float4 be = *(const float4*)(beta  + (tid << 2));
    float4 o;
    o.x = (v.x - mu) * inv * ga.x + be.x;
    o.y = (v.y - mu) * inv * ga.y + be.y;
    o.z = (v.z - mu) * inv * ga.z + be.z;
    o.w = (v.w - mu) * inv * ga.w + be.w;
    *(float4*)(out + (size_t)tk * DM + (tid << 2)) = o;
}

// ===========================================================================
extern "C" void kernel_launch(void* const* d_in, const int* in_sizes, int n_in,
                              void* d_out, int out_size)
{
    const float* Q  = (const float*)d_in[0];
    const float* K  = (const float*)d_in[1];
    const float* V  = (const float*)d_in[2];
    const unsigned char* mask = (const unsigned char*)d_in[3];
    const float* Wq = (const float*)d_in[4];
    const float* bq = (const float*)d_in[5];
    const float* Wk = (const float*)d_in[6];
    const float* bk = (const float*)d_in[7];
    const float* Wv = (const float*)d_in[8];
    const float* bv = (const float*)d_in[9];
    const float* Wo = (const float*)d_in[10];
    const float* bo = (const float*)d_in[11];
    const float* gamma = (const float*)d_in[12];
    const float* beta  = (const float*)d_in[13];

    float* out  = (float*)d_out;
    float* attn = out + ATTN_OFF;

    qkv_kernel<<<dim3(DM/128, TTOK/128, 3), 256>>>(Q, K, V, Wq, Wk, Wv, bq, bk, bv);
    scores_kernel<<<dim3(SEQ/128, SEQ/128, BHN), 256>>>(mask, attn);
    softmax_kernel<<<BHN * SEQ, 128>>>(attn);
    ctx_kernel<<<dim3(SEQ/128, BHN), 256>>>(attn);
    oproj_kernel<<<dim3(DM/128, TTOK/128), 256>>>(Wo, bo, Q);
    ln_kernel<<<TTOK, 256>>>(gamma, beta, out);
}